// round 17
// baseline (speedup 1.0000x reference)
#include <cuda_runtime.h>
#include <cuda_fp16.h>
#include <math_constants.h>
#include <mma.h>

using namespace nvcuda;

#define N_NODES   262144
#define D_IN      512
#define B_GRAPHS  256
#define GATES     2048      // 4*D_IN
#define K_COMB    1024      // combined K (h:512 | r:512)
#define STEPS     6
#define KITERS    (K_COMB / 32)   // 32

// ----------------- device scratch (no runtime allocation allowed) -----------
__device__ __align__(16) __half g_W16[GATES * K_COMB];    // fp16 combined weights (4 MB)
__device__ __align__(16) float  g_bias[GATES];
__device__ __align__(16) __half g_hr16[B_GRAPHS * 1024];  // fp16 [h | r] for GEMM
__device__ __align__(16) float  g_c[B_GRAPHS * D_IN];
__device__ __align__(16) float  g_gates[B_GRAPHS * GATES];
__device__ __align__(16) __half g_x16[(size_t)N_NODES * D_IN];  // 256 MB fp16 copy
__device__ int g_off[B_GRAPHS + 1];
__device__ unsigned g_barrier;                             // reset by attn0

// ----------------------------- helpers --------------------------------------
__device__ __forceinline__ float sigm(float v) {
    return 1.0f / (1.0f + __expf(-v));
}
__device__ __forceinline__ void cp_async16(void* smem_dst, const void* gmem_src) {
    unsigned s = (unsigned)__cvta_generic_to_shared(smem_dst);
    asm volatile("cp.async.cg.shared.global [%0], [%1], 16;" :: "r"(s), "l"(gmem_src) : "memory");
}
#define CP_COMMIT() asm volatile("cp.async.commit_group;" ::: "memory")

// Grid-wide barrier: all 256 blocks co-resident (occupancy 2, grid <= 296
// slots) -> spinning is deadlock-free.
__device__ __forceinline__ void grid_barrier(unsigned target) {
    __syncthreads();
    if (threadIdx.x == 0) {
        __threadfence();
        atomicAdd(&g_barrier, 1u);
        while (*((volatile unsigned*)&g_barrier) < target) { }
        __threadfence();
    }
    __syncthreads();
}

// ----------- prep kernel: weights(fp16) + bias + offsets, vectorized ---------
// 8 elements per thread: grid 1024 x 256 covers 2M weight elements.
__global__ void prep_w_kernel(const float* __restrict__ w_ih,
                              const float* __restrict__ w_hh,
                              const float* __restrict__ b_ih,
                              const float* __restrict__ b_hh,
                              const int*   __restrict__ batch) {
    const int t   = blockIdx.x * blockDim.x + threadIdx.x;   // 0 .. 262143
    const int idx = t * 8;
    const int n = idx >> 10;
    const int k = idx & 1023;          // multiple of 8

    float4 v0 = *(const float4*)(w_ih + n * 1024 + k);
    float4 v1 = *(const float4*)(w_ih + n * 1024 + k + 4);
    if (k < 512) {
        float4 u0 = *(const float4*)(w_hh + n * 512 + k);
        float4 u1 = *(const float4*)(w_hh + n * 512 + k + 4);
        v0.x += u0.x; v0.y += u0.y; v0.z += u0.z; v0.w += u0.w;
        v1.x += u1.x; v1.y += u1.y; v1.z += u1.z; v1.w += u1.w;
    }
    __half2 h0 = __floats2half2_rn(v0.x, v0.y);
    __half2 h1 = __floats2half2_rn(v0.z, v0.w);
    __half2 h2 = __floats2half2_rn(v1.x, v1.y);
    __half2 h3 = __floats2half2_rn(v1.z, v1.w);
    uint4 px;
    px.x = *(unsigned*)&h0; px.y = *(unsigned*)&h1;
    px.z = *(unsigned*)&h2; px.w = *(unsigned*)&h3;
    *(uint4*)(g_W16 + idx) = px;

    if (t < GATES) g_bias[t] = b_ih[t] + b_hh[t];
    if (t <= B_GRAPHS) {               // segment offsets: lower_bound
        int lo = 0, hi = N_NODES;
        while (lo < hi) {
            int mid = (lo + hi) >> 1;
            if (batch[mid] < t) lo = mid + 1; else hi = mid;
        }
        g_off[t] = lo;
    }
}

// ---------- attention step 0: one block per graph, fp32 + fp16 copy ----------
// Preamble computes h0 = lstm(0,0,0) from bias directly (no init kernel).
// Warp-per-node online softmax; col layout slot j*4+c <-> column 128*j+4*lane+c.
__global__ void __launch_bounds__(512, 2) attn0_kernel(const float* __restrict__ x) {
    const int b    = blockIdx.x;
    const int tid  = threadIdx.x;
    const int wid  = tid >> 5;
    const int lane = tid & 31;

    const int s0 = g_off[b];
    const int s1 = g_off[b + 1];

    __shared__ __align__(16) float sm_q[D_IN];
    __shared__ float  sm_m[16], sm_d[16], sm_scale[16];
    __shared__ __align__(16) float4 sm_r[16][128];

    // ---- closed-form step-0 LSTM: q0 = h0, c0 stored ----
    {
        float i = sigm(g_bias[tid]);
        float g = tanhf(g_bias[1024 + tid]);
        float o = sigm(g_bias[1536 + tid]);
        float c = i * g;
        float h = o * tanhf(c);
        g_c[b * D_IN + tid] = c;
        sm_q[tid] = h;
        g_hr16[b * 1024 + tid] = __float2half_rn(h);
        if (b == 0 && tid == 0) g_barrier = 0;   // reset for mega kernel
    }
    __syncthreads();
    const float4* q4 = (const float4*)sm_q;

    float m = -CUDART_INF_F, denom = 0.0f;
    float r[16];
    #pragma unroll
    for (int k = 0; k < 16; k++) r[k] = 0.0f;

    for (int n = s0 + wid; n < s1; n += 16) {
        const float4* xr = (const float4*)(x + (size_t)n * D_IN);
        float xv[16];
        #pragma unroll
        for (int j = 0; j < 4; j++) {
            float4 v = __ldcs(xr + j * 32 + lane);
            xv[j*4+0] = v.x; xv[j*4+1] = v.y;
            xv[j*4+2] = v.z; xv[j*4+3] = v.w;
        }
        {
            uint2* row16 = (uint2*)(g_x16 + (size_t)n * D_IN);
            #pragma unroll
            for (int j = 0; j < 4; j++) {
                __half2 h0 = __floats2half2_rn(xv[j*4+0], xv[j*4+1]);
                __half2 h1 = __floats2half2_rn(xv[j*4+2], xv[j*4+3]);
                uint2 px;
                px.x = *(unsigned*)&h0;
                px.y = *(unsigned*)&h1;
                row16[j * 32 + lane] = px;
            }
        }

        float p = 0.0f;
        #pragma unroll
        for (int j = 0; j < 4; j++) {
            float4 qv = q4[j * 32 + lane];
            p = fmaf(xv[j*4+0], qv.x, p);
            p = fmaf(xv[j*4+1], qv.y, p);
            p = fmaf(xv[j*4+2], qv.z, p);
            p = fmaf(xv[j*4+3], qv.w, p);
        }
        #pragma unroll
        for (int o = 16; o; o >>= 1) p += __shfl_xor_sync(0xffffffffu, p, o);

        const float mn = fmaxf(m, p);
        const float sc = __expf(m - mn);
        const float wg = __expf(p - mn);
        denom = fmaf(denom, sc, wg);
        #pragma unroll
        for (int k = 0; k < 16; k++) r[k] = fmaf(r[k], sc, wg * xv[k]);
        m = mn;
    }

    if (lane == 0) { sm_m[wid] = m; sm_d[wid] = denom; }
    #pragma unroll
    for (int j = 0; j < 4; j++)
        sm_r[wid][j * 32 + lane] =
            make_float4(r[j*4+0], r[j*4+1], r[j*4+2], r[j*4+3]);
    __syncthreads();

    float M = -CUDART_INF_F;
    #pragma unroll
    for (int w = 0; w < 16; w++) M = fmaxf(M, sm_m[w]);
    if (tid < 16)
        sm_scale[tid] = (sm_m[tid] == -CUDART_INF_F) ? 0.0f : __expf(sm_m[tid] - M);
    __syncthreads();

    float Dn = 0.0f, num = 0.0f;
    #pragma unroll
    for (int w = 0; w < 16; w++) {
        Dn  += sm_d[w] * sm_scale[w];
        num  = fmaf(((const float*)sm_r[w])[tid], sm_scale[w], num);
    }
    const float res = num / (Dn + 1e-16f);
    g_hr16[b * 1024 + 512 + tid] = __float2half_rn(res);
}

// --------- mega kernel: steps 1..5 (GEMM + LSTM + attention), 1 launch -------
// 256 blocks, all co-resident. Per step: ALL 256 blocks run the pipelined HMMA
// GEMM (64x32 tiles); grid barrier; every block runs LSTM preamble + fp16
// sweep for its graph; grid barrier. Cross-block data (gates, hr16) is read
// via L2-only paths (__ldcg / cp.async.cg) since L1 is not coherent in-kernel.
__global__ void __launch_bounds__(512, 2) mega_kernel(float* __restrict__ out) {
    extern __shared__ __align__(16) char smem_raw[];
    // GEMM overlay: sA[4][64][40] (20480 B) + sB[4][32][40] (10240 B)
    __half (*sA)[64][40] = (__half (*)[64][40])smem_raw;
    __half (*sB)[32][40] = (__half (*)[32][40])(smem_raw + 4 * 64 * 40 * 2);
    // attention overlay (35008 B)
    float* sm_q    = (float*)smem_raw;                     // 512 f
    float* sm_m    = (float*)(smem_raw + 2048);            // 16 f
    float* sm_d    = (float*)(smem_raw + 2048 + 64);       // 16 f
    float* sm_sc   = (float*)(smem_raw + 2048 + 128);      // 16 f
    float* sm_rbuf = (float*)(smem_raw + 2048 + 192);      // 16*512 f

    const int bid  = blockIdx.x;
    const int tid  = threadIdx.x;
    const int wid  = tid >> 5;
    const int lane = tid & 31;
    const int b    = bid;                   // graph id
    const int s0   = g_off[b];
    const int s1   = g_off[b + 1];

    // GEMM role (all 256 blocks): tile (gbm, gbn) of 64x32
    const int gbm = (bid >> 6) * 64;        // 4 row tiles
    const int gbn = (bid & 63) * 32;        // 64 col tiles
    const bool isA = (tid < 256);
    const bool isB = (tid >= 256 && tid < 384);
    const int lt   = isA ? tid : (tid - 256);
    const int lrow = lt >> 2;               // A: 0..63, B: 0..31
    const int lcol = (lt & 3) * 8;          // halves 0,8,16,24
    const __half* gsrc = isA ? (g_hr16 + (gbm + lrow) * K_COMB + lcol)
                             : (g_W16  + (gbn + lrow) * K_COMB + lcol);
    const int mt = wid & 3, nt = wid >> 2;  // warps 0..7 -> 16x16 output tile

    unsigned bar = 0;

    for (int s = 1; s <= STEPS - 1; s++) {
        // ================= GEMM phase: gates = hr16 @ W^T ====================
        {
            wmma::fragment<wmma::accumulator, 16, 16, 16, float> cf;
            wmma::fill_fragment(cf, 0.0f);

            auto issue = [&](int ks) {
                const int st = ks & 3;
                if (isA)      cp_async16(&sA[st][lrow][lcol], gsrc + ks * 32);
                else if (isB) cp_async16(&sB[st][lrow][lcol], gsrc + ks * 32);
                CP_COMMIT();
            };
            auto compute = [&](int st) {
                if (wid < 8) {
                    #pragma unroll
                    for (int kk = 0; kk < 32; kk += 16) {
                        wmma::fragment<wmma::matrix_a, 16, 16, 16, __half, wmma::row_major> af;
                        wmma::load_matrix_sync(af, &sA[st][mt * 16][kk], 40);
                        wmma::fragment<wmma::matrix_b, 16, 16, 16, __half, wmma::col_major> bf;
                        wmma::load_matrix_sync(bf, &sB[st][nt * 16][kk], 40);
                        wmma::mma_sync(cf, af, bf, cf);
                    }
                }
            };

            issue(0); issue(1); issue(2);
            int i = 0;
            for (; i < KITERS - 3; i++) {
                asm volatile("cp.async.wait_group 2;" ::: "memory");
                __syncthreads();
                issue(i + 3);
                compute(i & 3);
            }
            asm volatile("cp.async.wait_group 0;" ::: "memory");
            __syncthreads();
            for (; i < KITERS; i++) compute(i & 3);

            if (wid < 8)
                wmma::store_matrix_sync(&g_gates[(gbm + mt * 16) * GATES + gbn + nt * 16],
                                        cf, GATES, wmma::mem_row_major);
        }
        bar += B_GRAPHS; grid_barrier(bar);

        // ================= attention phase (graph b) =========================
        // LSTM cell preamble (gates via L2: other blocks wrote them)
        {
            const float* gr = g_gates + b * GATES + tid;
            const float iv = sigm(__ldcg(gr)          + g_bias[tid]);
            const float fv = sigm(__ldcg(gr + 512)    + g_bias[512 + tid]);
            const float gv = tanhf(__ldcg(gr + 1024)  + g_bias[1024 + tid]);
            const float ov = sigm(__ldcg(gr + 1536)   + g_bias[1536 + tid]);
            const int cidx = b * D_IN + tid;
            const float c = fv * g_c[cidx] + iv * gv;
            g_c[cidx] = c;
            const float h = ov * tanhf(c);
            sm_q[tid] = h;
            g_hr16[b * 1024 + tid] = __float2half_rn(h);
        }
        __syncthreads();

        float qf[16];
        #pragma unroll
        for (int k = 0; k < 8; k++) qf[k]     = sm_q[8 * lane + k];
        #pragma unroll
        for (int k = 0; k < 8; k++) qf[8 + k] = sm_q[256 + 8 * lane + k];

        float m = -CUDART_INF_F, denom = 0.0f;
        float r[16];
        #pragma unroll
        for (int k = 0; k < 16; k++) r[k] = 0.0f;

        for (int n = s0 + wid * 2; n < s1; n += 32) {
            const uint4* rowa = (const uint4*)(g_x16 + (size_t)n * D_IN);
            uint4 a0 = __ldcs(rowa + lane);
            uint4 a1 = __ldcs(rowa + 32 + lane);
            const bool has_b = (n + 1) < s1;
            uint4 b0, b1;
            if (has_b) {
                const uint4* rowb = (const uint4*)(g_x16 + (size_t)(n + 1) * D_IN);
                b0 = __ldcs(rowb + lane);
                b1 = __ldcs(rowb + 32 + lane);
            }

            float xf[16];
            {
                const unsigned* u = (const unsigned*)&a0;
                #pragma unroll
                for (int t = 0; t < 4; t++) {
                    float2 f = __half22float2(*(const __half2*)&u[t]);
                    xf[t*2+0] = f.x; xf[t*2+1] = f.y;
                }
                const unsigned* v = (const unsigned*)&a1;
                #pragma unroll
                for (int t = 0; t < 4; t++) {
                    float2 f = __half22float2(*(const __half2*)&v[t]);
                    xf[8+t*2+0] = f.x; xf[8+t*2+1] = f.y;
                }
            }
            float p = 0.0f;
            #pragma unroll
            for (int k = 0; k < 16; k++) p = fmaf(xf[k], qf[k], p);
            #pragma unroll
            for (int o = 16; o; o >>= 1) p += __shfl_xor_sync(0xffffffffu, p, o);
            float mn = fmaxf(m, p);
            float sc = __expf(m - mn);
            float wg = __expf(p - mn);
            denom = fmaf(denom, sc, wg);
            #pragma unroll
            for (int k = 0; k < 16; k++) r[k] = fmaf(r[k], sc, wg * xf[k]);
            m = mn;

            if (has_b) {
                float yf[16];
                {
                    const unsigned* u = (const unsigned*)&b0;
                    #pragma unroll
                    for (int t = 0; t < 4; t++) {
                        float2 f = __half22float2(*(const __half2*)&u[t]);
                        yf[t*2+0] = f.x; yf[t*2+1] = f.y;
                    }
                    const unsigned* v = (const unsigned*)&b1;
                    #pragma unroll
                    for (int t = 0; t < 4; t++) {
                        float2 f = __half22float2(*(const __half2*)&v[t]);
                        yf[8+t*2+0] = f.x; yf[8+t*2+1] = f.y;
                    }
                }
                float pb = 0.0f;
                #pragma unroll
                for (int k = 0; k < 16; k++) pb = fmaf(yf[k], qf[k], pb);
                #pragma unroll
                for (int o = 16; o; o >>= 1) pb += __shfl_xor_sync(0xffffffffu, pb, o);
                mn = fmaxf(m, pb);
                sc = __expf(m - mn);
                wg = __expf(pb - mn);
                denom = fmaf(denom, sc, wg);
                #pragma unroll
                for (int k = 0; k < 16; k++) r[k] = fmaf(r[k], sc, wg * yf[k]);
                m = mn;
            }
        }

        if (lane == 0) { sm_m[wid] = m; sm_d[wid] = denom; }
        {
            float* dst = sm_rbuf + wid * 512;
            #pragma unroll
            for (int k = 0; k < 8; k++) dst[8 * lane + k]       = r[k];
            #pragma unroll
            for (int k = 0; k < 8; k++) dst[256 + 8 * lane + k] = r[8 + k];
        }
        __syncthreads();

        float M = -CUDART_INF_F;
        #pragma unroll
        for (int w = 0; w < 16; w++) M = fmaxf(M, sm_m[w]);
        if (tid < 16)
            sm_sc[tid] = (sm_m[tid] == -CUDART_INF_F) ? 0.0f : __expf(sm_m[tid] - M);
        __syncthreads();

        float Dn = 0.0f, num = 0.0f;
        #pragma unroll
        for (int w = 0; w < 16; w++) {
            Dn  += sm_d[w] * sm_sc[w];
            num  = fmaf(sm_rbuf[w * 512 + tid], sm_sc[w], num);
        }
        const float res = num / (Dn + 1e-16f);
        g_hr16[b * 1024 + 512 + tid] = __float2half_rn(res);

        if (s == STEPS - 1) {
            out[b * 1024 + tid]       = sm_q[tid];   // h half
            out[b * 1024 + 512 + tid] = res;         // r half
        } else {
            bar += B_GRAPHS; grid_barrier(bar);
        }
    }
}

// ------------------------------- launch --------------------------------------
extern "C" void kernel_launch(void* const* d_in, const int* in_sizes, int n_in,
                              void* d_out, int out_size) {
    const float* x     = (const float*)d_in[0];
    const int*   batch = (const int*)d_in[1];
    const float* w_ih  = (const float*)d_in[2];
    const float* w_hh  = (const float*)d_in[3];
    const float* b_ih  = (const float*)d_in[4];
    const float* b_hh  = (const float*)d_in[5];
    float* out = (float*)d_out;

    const int mega_smem = 40960;   // >= max(GEMM 30720, attention 35008)

    prep_w_kernel<<<(GATES * K_COMB) / 8 / 256, 256>>>(w_ih, w_hh, b_ih, b_hh, batch);
    attn0_kernel<<<B_GRAPHS, 512>>>(x);
    mega_kernel<<<B_GRAPHS, 512, mega_smem>>>(out);
}